// round 2
// baseline (speedup 1.0000x reference)
#include <cuda_runtime.h>
#include <math.h>

// Problem constants
#define BATCH 2
#define SEQ   2048
#define ISZ   1024
#define NHEAD 16
#define HDIM  64
#define ROWS  (BATCH*SEQ)      // 4096

// ---------------------------------------------------------------------------
// Scratch (device globals: allocation-free per harness rules)
// ---------------------------------------------------------------------------
__device__ float g_nq[(size_t)ROWS*ISZ];
__device__ float g_nk[(size_t)ROWS*ISZ];
__device__ float g_nv[(size_t)ROWS*ISZ];
__device__ float g_qw[(size_t)ROWS*ISZ];
__device__ float g_kw[(size_t)ROWS*ISZ];
__device__ float g_vw[(size_t)ROWS*ISZ];
__device__ float g_ao[(size_t)ROWS*ISZ];

// ---------------------------------------------------------------------------
// LayerNorm: one block per row, 3 tensors in one launch (grid = 3*4096)
// ---------------------------------------------------------------------------
__global__ __launch_bounds__(256) void ln3_kernel(
    const float* __restrict__ q, const float* __restrict__ k,
    const float* __restrict__ v, const float* __restrict__ g,
    const float* __restrict__ beta)
{
    __shared__ float sbuf[8];
    int which = blockIdx.x >> 12;          // /4096
    int row   = blockIdx.x & 4095;
    const float* x =
        (which == 0 ? q : which == 1 ? k : v) + (size_t)row * ISZ;
    float* out =
        (which == 0 ? g_nq : which == 1 ? g_nk : g_nv) + (size_t)row * ISZ;

    int tid  = threadIdx.x;
    int lane = tid & 31, wid = tid >> 5;

    float vals[4];
    float s = 0.f;
#pragma unroll
    for (int i = 0; i < 4; i++) { vals[i] = x[tid + i * 256]; s += vals[i]; }

#pragma unroll
    for (int o = 16; o > 0; o >>= 1) s += __shfl_xor_sync(0xffffffffu, s, o);
    if (lane == 0) sbuf[wid] = s;
    __syncthreads();
    if (tid < 32) {
        float t = (tid < 8) ? sbuf[tid] : 0.f;
#pragma unroll
        for (int o = 4; o > 0; o >>= 1) t += __shfl_xor_sync(0xffffffffu, t, o);
        if (tid == 0) sbuf[0] = t;
    }
    __syncthreads();
    float mu = sbuf[0] * (1.f / ISZ);
    __syncthreads();

    float sq = 0.f;
#pragma unroll
    for (int i = 0; i < 4; i++) { float d = vals[i] - mu; sq += d * d; }
#pragma unroll
    for (int o = 16; o > 0; o >>= 1) sq += __shfl_xor_sync(0xffffffffu, sq, o);
    if (lane == 0) sbuf[wid] = sq;
    __syncthreads();
    if (tid < 32) {
        float t = (tid < 8) ? sbuf[tid] : 0.f;
#pragma unroll
        for (int o = 4; o > 0; o >>= 1) t += __shfl_xor_sync(0xffffffffu, t, o);
        if (tid == 0) sbuf[0] = t;
    }
    __syncthreads();
    float var  = sbuf[0] * (1.f / ISZ);
    float rstd = rsqrtf(var + 1e-5f);

#pragma unroll
    for (int i = 0; i < 4; i++) {
        int idx = tid + i * 256;
        out[idx] = (vals[i] - mu) * rstd * g[idx] + beta[idx];
    }
}

// ---------------------------------------------------------------------------
// SGEMM: C[M,N] = (A[M,K] @ W[K,N] + bias[N]) * mask[row]
// 128x128x16 tiles, 256 threads, 8x8 per-thread micro-tile
// ---------------------------------------------------------------------------
#define BM 128
#define BN 128
#define BK 16

__global__ __launch_bounds__(256) void gemm_bias_mask(
    const float* __restrict__ A, const float* __restrict__ W,
    const float* __restrict__ bias, const float* __restrict__ mask,
    float* __restrict__ C, int M, int N, int Kd)
{
    __shared__ __align__(16) float As[BK][BM];
    __shared__ __align__(16) float Bs[BK][BN];

    int tid = threadIdx.x;
    int bm = blockIdx.y * BM, bn = blockIdx.x * BN;
    int tx = tid & 15, ty = tid >> 4;

    float acc[8][8];
#pragma unroll
    for (int i = 0; i < 8; i++)
#pragma unroll
        for (int j = 0; j < 8; j++) acc[i][j] = 0.f;

    int arow0 = tid >> 2;   // A: 128 rows x 4 float4/row
    int aq    = tid & 3;
    int brow0 = tid >> 5;   // B: 16 rows x 32 float4/row
    int bq    = tid & 31;

    for (int k0 = 0; k0 < Kd; k0 += BK) {
#pragma unroll
        for (int i = 0; i < 2; i++) {
            int r = arow0 + i * 64;
            float4 a = *(const float4*)(A + (size_t)(bm + r) * Kd + k0 + aq * 4);
            As[aq * 4 + 0][r] = a.x;
            As[aq * 4 + 1][r] = a.y;
            As[aq * 4 + 2][r] = a.z;
            As[aq * 4 + 3][r] = a.w;
        }
#pragma unroll
        for (int i = 0; i < 2; i++) {
            int r = brow0 + i * 8;
            *(float4*)(&Bs[r][bq * 4]) =
                *(const float4*)(W + (size_t)(k0 + r) * N + bn + bq * 4);
        }
        __syncthreads();

#pragma unroll
        for (int k = 0; k < BK; k++) {
            float ra[8], rb[8];
            *(float4*)(ra)     = *(float4*)(&As[k][ty * 8]);
            *(float4*)(ra + 4) = *(float4*)(&As[k][ty * 8 + 4]);
            *(float4*)(rb)     = *(float4*)(&Bs[k][tx * 8]);
            *(float4*)(rb + 4) = *(float4*)(&Bs[k][tx * 8 + 4]);
#pragma unroll
            for (int i = 0; i < 8; i++)
#pragma unroll
                for (int j = 0; j < 8; j++) acc[i][j] += ra[i] * rb[j];
        }
        __syncthreads();
    }

#pragma unroll
    for (int i = 0; i < 8; i++) {
        int row = bm + ty * 8 + i;
        float mk = mask[row];
#pragma unroll
        for (int j = 0; j < 8; j += 4) {
            int col = bn + tx * 8 + j;
            float4 o;
            o.x = (acc[i][j + 0] + bias[col + 0]) * mk;
            o.y = (acc[i][j + 1] + bias[col + 1]) * mk;
            o.z = (acc[i][j + 2] + bias[col + 2]) * mk;
            o.w = (acc[i][j + 3] + bias[col + 3]) * mk;
            *(float4*)(C + (size_t)row * N + col) = o;
        }
    }
}

// ---------------------------------------------------------------------------
// Causal flash attention. Block = (b,h, 64-row q-tile). 256 threads:
// thread (row = tid/4, sub = tid%4) owns score/out cols {4*jj + sub}.
// Tiles padded to stride 68 floats: conflict-free for all access patterns.
// ---------------------------------------------------------------------------
#define PAD 68

__global__ __launch_bounds__(256) void attn_kernel(
    const float* __restrict__ Qw, const float* __restrict__ Kw,
    const float* __restrict__ Vw, float* __restrict__ Out)
{
    extern __shared__ float sm[];
    float* Qs = sm;
    float* Ks = Qs + 64 * PAD;
    float* Vs = Ks + 64 * PAD;
    float* Ps = Vs + 64 * PAD;

    int qt = blockIdx.x;            // q tile 0..31
    int bh = blockIdx.y;            // 0..31
    int b = bh >> 4, h = bh & 15;

    int tid = threadIdx.x;
    int row = tid >> 2, sub = tid & 3;

    size_t tokBase = (size_t)b * SEQ;
    int colBase = h * HDIM;
    int q0 = qt * 64;

    // load Q tile (64 x 64)
#pragma unroll
    for (int i = 0; i < 4; i++) {
        int p = i * 256 + tid;
        int r = p >> 4, f4 = p & 15;
        *(float4*)(&Qs[r * PAD + f4 * 4]) =
            *(const float4*)(Qw + (tokBase + q0 + r) * ISZ + colBase + f4 * 4);
    }

    float m = -1e30f, l = 0.f;
    float acc[16];
#pragma unroll
    for (int j = 0; j < 16; j++) acc[j] = 0.f;
    const float scale = 0.125f;     // 1/sqrt(64)

    for (int jt = 0; jt <= qt; jt++) {
        __syncthreads();            // prev-iter consumers done before overwrite
        int k0 = jt * 64;
#pragma unroll
        for (int i = 0; i < 4; i++) {
            int p = i * 256 + tid;
            int r = p >> 4, f4 = p & 15;
            *(float4*)(&Ks[r * PAD + f4 * 4]) =
                *(const float4*)(Kw + (tokBase + k0 + r) * ISZ + colBase + f4 * 4);
            *(float4*)(&Vs[r * PAD + f4 * 4]) =
                *(const float4*)(Vw + (tokBase + k0 + r) * ISZ + colBase + f4 * 4);
        }
        __syncthreads();

        // scores for this thread's 16 columns
        float sc[16];
#pragma unroll
        for (int jj = 0; jj < 16; jj++) {
            int c = jj * 4 + sub;
            float d = 0.f;
#pragma unroll
            for (int k = 0; k < 64; k++)
                d += Qs[row * PAD + k] * Ks[c * PAD + k];
            d *= scale;
            if (jt == qt && c > row) d = -1e30f;   // causal
            sc[jj] = d;
        }

        // online softmax (4-lane reduce within row group)
        float tmax = sc[0];
#pragma unroll
        for (int jj = 1; jj < 16; jj++) tmax = fmaxf(tmax, sc[jj]);
        tmax = fmaxf(tmax, __shfl_xor_sync(0xffffffffu, tmax, 1));
        tmax = fmaxf(tmax, __shfl_xor_sync(0xffffffffu, tmax, 2));

        float mnew = fmaxf(m, tmax);
        float corr = __expf(m - mnew);
        float tsum = 0.f;
#pragma unroll
        for (int jj = 0; jj < 16; jj++) {
            float p = __expf(sc[jj] - mnew);
            tsum += p;
            Ps[row * PAD + jj * 4 + sub] = p;
        }
        tsum += __shfl_xor_sync(0xffffffffu, tsum, 1);
        tsum += __shfl_xor_sync(0xffffffffu, tsum, 2);

        l = l * corr + tsum;
        m = mnew;
#pragma unroll
        for (int jj = 0; jj < 16; jj++) acc[jj] *= corr;
        __syncthreads();            // Ps visible to all row owners

        // O += P @ V
#pragma unroll 4
        for (int k = 0; k < 64; k++) {
            float p = Ps[row * PAD + k];
#pragma unroll
            for (int jj = 0; jj < 16; jj++)
                acc[jj] += p * Vs[k * PAD + jj * 4 + sub];
        }
    }

    float inv = 1.f / l;
#pragma unroll
    for (int jj = 0; jj < 16; jj++) {
        Out[(tokBase + q0 + row) * ISZ + colBase + jj * 4 + sub] = acc[jj] * inv;
    }
}

// ---------------------------------------------------------------------------
// Launch
// ---------------------------------------------------------------------------
static float* symaddr_nq()  { void* p; cudaGetSymbolAddress(&p, g_nq); return (float*)p; }
static float* symaddr_nk()  { void* p; cudaGetSymbolAddress(&p, g_nk); return (float*)p; }
static float* symaddr_nv()  { void* p; cudaGetSymbolAddress(&p, g_nv); return (float*)p; }
static float* symaddr_qw()  { void* p; cudaGetSymbolAddress(&p, g_qw); return (float*)p; }
static float* symaddr_kw()  { void* p; cudaGetSymbolAddress(&p, g_kw); return (float*)p; }
static float* symaddr_vw()  { void* p; cudaGetSymbolAddress(&p, g_vw); return (float*)p; }
static float* symaddr_ao()  { void* p; cudaGetSymbolAddress(&p, g_ao); return (float*)p; }

extern "C" void kernel_launch(void* const* d_in, const int* in_sizes, int n_in,
                              void* d_out, int out_size)
{
    // metadata order:
    // 0 q, 1 k, 2 v, 3 q_mask, 4 kv_mask, 5 a_mask,
    // 6 ln_g, 7 ln_b, 8 Wq, 9 bq, 10 Wk, 11 bk, 12 Wv, 13 bv, 14 Wo, 15 bo
    const float* q       = (const float*)d_in[0];
    const float* k       = (const float*)d_in[1];
    const float* v       = (const float*)d_in[2];
    const float* q_mask  = (const float*)d_in[3];
    const float* kv_mask = (const float*)d_in[4];
    const float* ln_g    = (const float*)d_in[6];
    const float* ln_b    = (const float*)d_in[7];
    const float* Wq      = (const float*)d_in[8];
    const float* bq      = (const float*)d_in[9];
    const float* Wk      = (const float*)d_in[10];
    const float* bk      = (const float*)d_in[11];
    const float* Wv      = (const float*)d_in[12];
    const float* bv      = (const float*)d_in[13];
    const float* Wo      = (const float*)d_in[14];
    const float* bo      = (const float*)d_in[15];
    float* out = (float*)d_out;

    float* nq = symaddr_nq();
    float* nk = symaddr_nk();
    float* nv = symaddr_nv();
    float* qw = symaddr_qw();
    float* kw = symaddr_kw();
    float* vw = symaddr_vw();
    float* ao = symaddr_ao();

    // 1) LayerNorm q,k,v
    ln3_kernel<<<3 * ROWS, 256>>>(q, k, v, ln_g, ln_b);

    // 2) QKV projections (+bias, *mask)
    dim3 ggrid(ISZ / BN, ROWS / BM);
    gemm_bias_mask<<<ggrid, 256>>>(nq, Wq, bq, q_mask,  qw, ROWS, ISZ, ISZ);
    gemm_bias_mask<<<ggrid, 256>>>(nk, Wk, bk, kv_mask, kw, ROWS, ISZ, ISZ);
    gemm_bias_mask<<<ggrid, 256>>>(nv, Wv, bv, kv_mask, vw, ROWS, ISZ, ISZ);

    // 3) Causal flash attention
    int smem_bytes = 4 * 64 * PAD * (int)sizeof(float);   // 69632
    cudaFuncSetAttribute(attn_kernel,
                         cudaFuncAttributeMaxDynamicSharedMemorySize, smem_bytes);
    dim3 agrid(SEQ / 64, BATCH * NHEAD);
    attn_kernel<<<agrid, 256, smem_bytes>>>(qw, kw, vw, ao);

    // 4) Output projection (+bias, *kv_mask) straight into d_out
    gemm_bias_mask<<<ggrid, 256>>>(ao, Wo, bo, kv_mask, out, ROWS, ISZ, ISZ);
}

// round 3
// speedup vs baseline: 1.2581x; 1.2581x over previous
#include <cuda_runtime.h>
#include <math.h>
#include <stdint.h>

// Problem constants
#define BATCH 2
#define SEQ   2048
#define ISZ   1024
#define NHEAD 16
#define HDIM  64
#define ROWS  (BATCH*SEQ)      // 4096

// ---------------------------------------------------------------------------
// Scratch (device globals: allocation-free per harness rules)
// ---------------------------------------------------------------------------
__device__ float g_nq[(size_t)ROWS*ISZ];
__device__ float g_nk[(size_t)ROWS*ISZ];
__device__ float g_nv[(size_t)ROWS*ISZ];
__device__ float g_qw[(size_t)ROWS*ISZ];
__device__ float g_kw[(size_t)ROWS*ISZ];
__device__ float g_vw[(size_t)ROWS*ISZ];
__device__ float g_ao[(size_t)ROWS*ISZ];

// ---------------------------------------------------------------------------
// cp.async helpers
// ---------------------------------------------------------------------------
__device__ __forceinline__ uint32_t smem_u32(const void* p) {
    return (uint32_t)__cvta_generic_to_shared(p);
}
__device__ __forceinline__ void cp_async4(uint32_t dst, const void* src) {
    asm volatile("cp.async.ca.shared.global [%0], [%1], 4;\n" :: "r"(dst), "l"(src));
}
__device__ __forceinline__ void cp_async16(uint32_t dst, const void* src) {
    asm volatile("cp.async.cg.shared.global [%0], [%1], 16;\n" :: "r"(dst), "l"(src));
}
__device__ __forceinline__ void cp_commit() {
    asm volatile("cp.async.commit_group;\n");
}
__device__ __forceinline__ void cp_wait1() {
    asm volatile("cp.async.wait_group 1;\n");
}
__device__ __forceinline__ void cp_wait0() {
    asm volatile("cp.async.wait_group 0;\n");
}

// ---------------------------------------------------------------------------
// LayerNorm: one block per row, 3 tensors in one launch (grid = 3*4096)
// ---------------------------------------------------------------------------
__global__ __launch_bounds__(256) void ln3_kernel(
    const float* __restrict__ q, const float* __restrict__ k,
    const float* __restrict__ v, const float* __restrict__ g,
    const float* __restrict__ beta)
{
    __shared__ float sbuf[8];
    int which = blockIdx.x >> 12;          // /4096
    int row   = blockIdx.x & 4095;
    const float* x =
        (which == 0 ? q : which == 1 ? k : v) + (size_t)row * ISZ;
    float* out =
        (which == 0 ? g_nq : which == 1 ? g_nk : g_nv) + (size_t)row * ISZ;

    int tid  = threadIdx.x;
    int lane = tid & 31, wid = tid >> 5;

    float vals[4];
    float s = 0.f;
#pragma unroll
    for (int i = 0; i < 4; i++) { vals[i] = x[tid + i * 256]; s += vals[i]; }

#pragma unroll
    for (int o = 16; o > 0; o >>= 1) s += __shfl_xor_sync(0xffffffffu, s, o);
    if (lane == 0) sbuf[wid] = s;
    __syncthreads();
    if (tid < 32) {
        float t = (tid < 8) ? sbuf[tid] : 0.f;
#pragma unroll
        for (int o = 4; o > 0; o >>= 1) t += __shfl_xor_sync(0xffffffffu, t, o);
        if (tid == 0) sbuf[0] = t;
    }
    __syncthreads();
    float mu = sbuf[0] * (1.f / ISZ);
    __syncthreads();

    float sq = 0.f;
#pragma unroll
    for (int i = 0; i < 4; i++) { float d = vals[i] - mu; sq += d * d; }
#pragma unroll
    for (int o = 16; o > 0; o >>= 1) sq += __shfl_xor_sync(0xffffffffu, sq, o);
    if (lane == 0) sbuf[wid] = sq;
    __syncthreads();
    if (tid < 32) {
        float t = (tid < 8) ? sbuf[tid] : 0.f;
#pragma unroll
        for (int o = 4; o > 0; o >>= 1) t += __shfl_xor_sync(0xffffffffu, t, o);
        if (tid == 0) sbuf[0] = t;
    }
    __syncthreads();
    float var  = sbuf[0] * (1.f / ISZ);
    float rstd = rsqrtf(var + 1e-5f);

#pragma unroll
    for (int i = 0; i < 4; i++) {
        int idx = tid + i * 256;
        out[idx] = (vals[i] - mu) * rstd * g[idx] + beta[idx];
    }
}

// ---------------------------------------------------------------------------
// SGEMM with cp.async double buffering.
// C[M,N] = (A[M,K] @ W[K,N] + bias[N]) * mask[row]
// 128x128x16 tiles, 256 threads, 8x8 per-thread micro-tile.
// A in smem row-major, stride 17 (conflict-free broadcast reads).
// B in smem row-major [16][128].
// ---------------------------------------------------------------------------
#define BM 128
#define BN 128
#define BK 16
#define ASTR 17

__global__ __launch_bounds__(256, 2) void gemm_bias_mask(
    const float* __restrict__ A, const float* __restrict__ W,
    const float* __restrict__ bias, const float* __restrict__ mask,
    float* __restrict__ C, int M, int N, int Kd)
{
    __shared__ __align__(16) float As[2][BM * ASTR];   // 2 * 8704 B
    __shared__ __align__(16) float Bs[2][BK * BN];     // 2 * 8192 B

    int tid = threadIdx.x;
    int bm = blockIdx.y * BM, bn = blockIdx.x * BN;
    int tx = tid & 15, ty = tid >> 4;

    // A loader mapping: thread -> (row am, half ah) : 8 floats of a 16-float row
    int am = tid >> 1, ah = tid & 1;
    const float* Aptr = A + (size_t)(bm + am) * Kd + ah * 8;
    uint32_t adst0 = smem_u32(&As[0][am * ASTR + ah * 8]);
    uint32_t adst1 = smem_u32(&As[1][am * ASTR + ah * 8]);

    // B loader mapping: thread -> (row br, col group bc) : 8 floats
    int br = tid >> 4, bc = tid & 15;
    const float* Wptr = W + (size_t)br * N + bn + bc * 8;
    uint32_t bdst0 = smem_u32(&Bs[0][br * BN + bc * 8]);
    uint32_t bdst1 = smem_u32(&Bs[1][br * BN + bc * 8]);

    float acc[8][8];
#pragma unroll
    for (int i = 0; i < 8; i++)
#pragma unroll
        for (int j = 0; j < 8; j++) acc[i][j] = 0.f;

    const int ntiles = Kd / BK;   // 64

    // prefetch tile 0 into buffer 0
    {
        const float* srcA = Aptr;
#pragma unroll
        for (int j = 0; j < 8; j++) cp_async4(adst0 + j * 4, srcA + j);
        const float* srcB = Wptr;
        cp_async16(bdst0, srcB);
        cp_async16(bdst0 + 16, srcB + 4);
        cp_commit();
    }

    for (int t = 0; t < ntiles; t++) {
        if (t + 1 < ntiles) {
            // prefetch next tile into the other buffer
            uint32_t ad = ((t + 1) & 1) ? adst1 : adst0;
            uint32_t bd = ((t + 1) & 1) ? bdst1 : bdst0;
            const float* srcA = Aptr + (t + 1) * BK;
#pragma unroll
            for (int j = 0; j < 8; j++) cp_async4(ad + j * 4, srcA + j);
            const float* srcB = Wptr + (size_t)(t + 1) * BK * N;
            cp_async16(bd, srcB);
            cp_async16(bd + 16, srcB + 4);
            cp_commit();
            cp_wait1();
        } else {
            cp_wait0();
        }
        __syncthreads();

        const float* as = As[t & 1];
        const float* bs = Bs[t & 1];

#pragma unroll
        for (int k = 0; k < BK; k++) {
            float ra[8], rb[8];
#pragma unroll
            for (int i = 0; i < 8; i++) ra[i] = as[(ty * 8 + i) * ASTR + k];
            *(float4*)(rb)     = *(const float4*)(&bs[k * BN + tx * 8]);
            *(float4*)(rb + 4) = *(const float4*)(&bs[k * BN + tx * 8 + 4]);
#pragma unroll
            for (int i = 0; i < 8; i++)
#pragma unroll
                for (int j = 0; j < 8; j++) acc[i][j] += ra[i] * rb[j];
        }
        __syncthreads();
    }

#pragma unroll
    for (int i = 0; i < 8; i++) {
        int row = bm + ty * 8 + i;
        float mk = mask[row];
#pragma unroll
        for (int j = 0; j < 8; j += 4) {
            int col = bn + tx * 8 + j;
            float4 o;
            o.x = (acc[i][j + 0] + bias[col + 0]) * mk;
            o.y = (acc[i][j + 1] + bias[col + 1]) * mk;
            o.z = (acc[i][j + 2] + bias[col + 2]) * mk;
            o.w = (acc[i][j + 3] + bias[col + 3]) * mk;
            *(float4*)(C + (size_t)row * N + col) = o;
        }
    }
}

// ---------------------------------------------------------------------------
// Causal flash attention, register-tiled.
// Block = (b,h, 64-row q-tile), 256 threads as 16x16 grid.
// Thread (ty,tx): rows ty*4+i (i=0..3), cols tx+16*j (j=0..3).
// All smem arrays stride 66: hot-loop loads are conflict-free
//  (row-indexed loads broadcast; col loads hit 16 distinct even banks).
// ---------------------------------------------------------------------------
#define APAD 66

__global__ __launch_bounds__(256) void attn_kernel(
    const float* __restrict__ Qw, const float* __restrict__ Kw,
    const float* __restrict__ Vw, float* __restrict__ Out)
{
    extern __shared__ float sm[];
    float* Qs = sm;                    // 64 x APAD
    float* Ks = Qs + 64 * APAD;
    float* Vs = Ks + 64 * APAD;
    float* Ps = Vs + 64 * APAD;

    int qt = blockIdx.x;            // q tile 0..31
    int bh = blockIdx.y;            // 0..31
    int b = bh >> 4, h = bh & 15;

    int tid = threadIdx.x;
    int tx = tid & 15, ty = tid >> 4;

    size_t tokBase = (size_t)b * SEQ;
    int colBase = h * HDIM;
    int q0 = qt * 64;

    // load Q tile (64 x 64) -> Qs[r][k]
#pragma unroll
    for (int i = 0; i < 4; i++) {
        int p = i * 256 + tid;
        int r = p >> 4, f4 = p & 15;
        float4 qv = *(const float4*)(Qw + (tokBase + q0 + r) * ISZ + colBase + f4 * 4);
        Qs[r * APAD + f4 * 4 + 0] = qv.x;
        Qs[r * APAD + f4 * 4 + 1] = qv.y;
        Qs[r * APAD + f4 * 4 + 2] = qv.z;
        Qs[r * APAD + f4 * 4 + 3] = qv.w;
    }

    float m[4], l[4], acc[4][4];
#pragma unroll
    for (int i = 0; i < 4; i++) {
        m[i] = -3e38f; l[i] = 0.f;
#pragma unroll
        for (int j = 0; j < 4; j++) acc[i][j] = 0.f;
    }
    const float scale = 0.125f;     // 1/sqrt(64)

    for (int jt = 0; jt <= qt; jt++) {
        __syncthreads();            // prev-iter consumers done before overwrite
        int k0 = jt * 64;
#pragma unroll
        for (int i = 0; i < 4; i++) {
            int p = i * 256 + tid;
            int r = p >> 4, f4 = p & 15;
            float4 kv = *(const float4*)(Kw + (tokBase + k0 + r) * ISZ + colBase + f4 * 4);
            Ks[r * APAD + f4 * 4 + 0] = kv.x;
            Ks[r * APAD + f4 * 4 + 1] = kv.y;
            Ks[r * APAD + f4 * 4 + 2] = kv.z;
            Ks[r * APAD + f4 * 4 + 3] = kv.w;
            float4 vv = *(const float4*)(Vw + (tokBase + k0 + r) * ISZ + colBase + f4 * 4);
            Vs[r * APAD + f4 * 4 + 0] = vv.x;
            Vs[r * APAD + f4 * 4 + 1] = vv.y;
            Vs[r * APAD + f4 * 4 + 2] = vv.z;
            Vs[r * APAD + f4 * 4 + 3] = vv.w;
        }
        __syncthreads();

        // scores: 4x4 micro-tile, S = Q @ K^T
        float s4[4][4];
#pragma unroll
        for (int i = 0; i < 4; i++)
#pragma unroll
            for (int j = 0; j < 4; j++) s4[i][j] = 0.f;

#pragma unroll 8
        for (int k = 0; k < 64; k++) {
            float ra[4], rb[4];
#pragma unroll
            for (int i = 0; i < 4; i++) ra[i] = Qs[(ty * 4 + i) * APAD + k];
#pragma unroll
            for (int j = 0; j < 4; j++) rb[j] = Ks[(tx + 16 * j) * APAD + k];
#pragma unroll
            for (int i = 0; i < 4; i++)
#pragma unroll
                for (int j = 0; j < 4; j++) s4[i][j] += ra[i] * rb[j];
        }

        bool diag = (jt == qt);
#pragma unroll
        for (int i = 0; i < 4; i++) {
            int R = ty * 4 + i;
            float mx = -3e38f;
#pragma unroll
            for (int j = 0; j < 4; j++) {
                float v = s4[i][j] * scale;
                if (diag && (tx + 16 * j) > R) v = -3e38f;
                s4[i][j] = v;
                mx = fmaxf(mx, v);
            }
            // reduce max over the 16 column-owner lanes (same half-warp)
            mx = fmaxf(mx, __shfl_xor_sync(0xffffffffu, mx, 1));
            mx = fmaxf(mx, __shfl_xor_sync(0xffffffffu, mx, 2));
            mx = fmaxf(mx, __shfl_xor_sync(0xffffffffu, mx, 4));
            mx = fmaxf(mx, __shfl_xor_sync(0xffffffffu, mx, 8));

            float mnew = fmaxf(m[i], mx);
            float corr = __expf(m[i] - mnew);
            float ts = 0.f;
#pragma unroll
            for (int j = 0; j < 4; j++) {
                float pv = __expf(s4[i][j] - mnew);
                Ps[R * APAD + tx + 16 * j] = pv;
                ts += pv;
            }
            ts += __shfl_xor_sync(0xffffffffu, ts, 1);
            ts += __shfl_xor_sync(0xffffffffu, ts, 2);
            ts += __shfl_xor_sync(0xffffffffu, ts, 4);
            ts += __shfl_xor_sync(0xffffffffu, ts, 8);

            l[i] = l[i] * corr + ts;
            m[i] = mnew;
#pragma unroll
            for (int j = 0; j < 4; j++) acc[i][j] *= corr;
        }
        __syncthreads();            // Ps visible to all

        // O += P @ V  (4x4 micro-tile)
#pragma unroll 8
        for (int k2 = 0; k2 < 64; k2++) {
            float ra[4], rb[4];
#pragma unroll
            for (int i = 0; i < 4; i++) ra[i] = Ps[(ty * 4 + i) * APAD + k2];
#pragma unroll
            for (int j = 0; j < 4; j++) rb[j] = Vs[k2 * APAD + tx + 16 * j];
#pragma unroll
            for (int i = 0; i < 4; i++)
#pragma unroll
                for (int j = 0; j < 4; j++) acc[i][j] += ra[i] * rb[j];
        }
    }

#pragma unroll
    for (int i = 0; i < 4; i++) {
        float inv = 1.f / l[i];
        size_t rbase = (tokBase + q0 + ty * 4 + i) * ISZ + colBase;
#pragma unroll
        for (int j = 0; j < 4; j++) {
            Out[rbase + tx + 16 * j] = acc[i][j] * inv;
        }
    }
}

// ---------------------------------------------------------------------------
// Launch
// ---------------------------------------------------------------------------
static float* symaddr(const void* sym) { void* p; cudaGetSymbolAddress(&p, sym); return (float*)p; }

extern "C" void kernel_launch(void* const* d_in, const int* in_sizes, int n_in,
                              void* d_out, int out_size)
{
    // metadata order:
    // 0 q, 1 k, 2 v, 3 q_mask, 4 kv_mask, 5 a_mask,
    // 6 ln_g, 7 ln_b, 8 Wq, 9 bq, 10 Wk, 11 bk, 12 Wv, 13 bv, 14 Wo, 15 bo
    const float* q       = (const float*)d_in[0];
    const float* k       = (const float*)d_in[1];
    const float* v       = (const float*)d_in[2];
    const float* q_mask  = (const float*)d_in[3];
    const float* kv_mask = (const float*)d_in[4];
    const float* ln_g    = (const float*)d_in[6];
    const float* ln_b    = (const float*)d_in[7];
    const float* Wq      = (const float*)d_in[8];
    const float* bq      = (const float*)d_in[9];
    const float* Wk      = (const float*)d_in[10];
    const float* bk      = (const float*)d_in[11];
    const float* Wv      = (const float*)d_in[12];
    const float* bv      = (const float*)d_in[13];
    const float* Wo      = (const float*)d_in[14];
    const float* bo      = (const float*)d_in[15];
    float* out = (float*)d_out;

    float* nq = symaddr(g_nq);
    float* nk = symaddr(g_nk);
    float* nv = symaddr(g_nv);
    float* qw = symaddr(g_qw);
    float* kw = symaddr(g_kw);
    float* vw = symaddr(g_vw);
    float* ao = symaddr(g_ao);

    // 1) LayerNorm q,k,v
    ln3_kernel<<<3 * ROWS, 256>>>(q, k, v, ln_g, ln_b);

    // 2) QKV projections (+bias, *mask)
    dim3 ggrid(ISZ / BN, ROWS / BM);
    gemm_bias_mask<<<ggrid, 256>>>(nq, Wq, bq, q_mask,  qw, ROWS, ISZ, ISZ);
    gemm_bias_mask<<<ggrid, 256>>>(nk, Wk, bk, kv_mask, kw, ROWS, ISZ, ISZ);
    gemm_bias_mask<<<ggrid, 256>>>(nv, Wv, bv, kv_mask, vw, ROWS, ISZ, ISZ);

    // 3) Causal flash attention
    int smem_bytes = 4 * 64 * APAD * (int)sizeof(float);   // 67584
    cudaFuncSetAttribute(attn_kernel,
                         cudaFuncAttributeMaxDynamicSharedMemorySize, smem_bytes);
    dim3 agrid(SEQ / 64, BATCH * NHEAD);
    attn_kernel<<<agrid, 256, smem_bytes>>>(qw, kw, vw, ao);

    // 4) Output projection (+bias, *kv_mask) straight into d_out
    gemm_bias_mask<<<ggrid, 256>>>(ao, Wo, bo, kv_mask, out, ROWS, ISZ, ISZ);
}

// round 5
// speedup vs baseline: 2.0845x; 1.6569x over previous
#include <cuda_runtime.h>
#include <cuda_bf16.h>
#include <math.h>
#include <stdint.h>

// Problem constants
#define BATCH 2
#define SEQ   2048
#define ISZ   1024
#define NHEAD 16
#define HDIM  64
#define ROWS  (BATCH*SEQ)      // 4096

typedef __nv_bfloat16 bf16;

// ---------------------------------------------------------------------------
// Scratch (device globals: allocation-free per harness rules)
// ---------------------------------------------------------------------------
__device__ bf16  g_xhi[(size_t)3*ROWS*ISZ];   // LN outputs hi (q,k,v)
__device__ bf16  g_xlo[(size_t)3*ROWS*ISZ];   // LN outputs lo
__device__ bf16  g_wth[(size_t)4*ISZ*ISZ];    // W^T hi (Wq,Wk,Wv,Wo)
__device__ bf16  g_wtl[(size_t)4*ISZ*ISZ];    // W^T lo
__device__ float g_qw[(size_t)ROWS*ISZ];
__device__ float g_kw[(size_t)ROWS*ISZ];
__device__ float g_vw[(size_t)ROWS*ISZ];
__device__ bf16  g_aoh[(size_t)ROWS*ISZ];     // attention out hi
__device__ bf16  g_aol[(size_t)ROWS*ISZ];     // attention out lo

// ---------------------------------------------------------------------------
// PTX helpers (Ampere-compatible: cp.async, ldmatrix, mma.sync)
// ---------------------------------------------------------------------------
__device__ __forceinline__ uint32_t smem_u32(const void* p) {
    return (uint32_t)__cvta_generic_to_shared(p);
}
__device__ __forceinline__ void cp_async16(uint32_t dst, const void* src) {
    asm volatile("cp.async.cg.shared.global [%0], [%1], 16;\n" :: "r"(dst), "l"(src));
}
__device__ __forceinline__ void cp_commit() {
    asm volatile("cp.async.commit_group;\n");
}
__device__ __forceinline__ void cp_wait1() {
    asm volatile("cp.async.wait_group 1;\n");
}
__device__ __forceinline__ void cp_wait0() {
    asm volatile("cp.async.wait_group 0;\n");
}
__device__ __forceinline__ void ldsm_x4(uint32_t& r0, uint32_t& r1,
                                        uint32_t& r2, uint32_t& r3, uint32_t a) {
    asm volatile("ldmatrix.sync.aligned.m8n8.x4.shared.b16 {%0,%1,%2,%3}, [%4];"
                 : "=r"(r0), "=r"(r1), "=r"(r2), "=r"(r3) : "r"(a));
}
__device__ __forceinline__ void ldsm_x2(uint32_t& r0, uint32_t& r1, uint32_t a) {
    asm volatile("ldmatrix.sync.aligned.m8n8.x2.shared.b16 {%0,%1}, [%2];"
                 : "=r"(r0), "=r"(r1) : "r"(a));
}
__device__ __forceinline__ void mma_bf16(float* d, const uint32_t* a, const uint32_t* b) {
    asm volatile("mma.sync.aligned.m16n8k16.row.col.f32.bf16.bf16.f32 "
                 "{%0,%1,%2,%3}, {%4,%5,%6,%7}, {%8,%9}, {%0,%1,%2,%3};"
                 : "+f"(d[0]), "+f"(d[1]), "+f"(d[2]), "+f"(d[3])
                 : "r"(a[0]), "r"(a[1]), "r"(a[2]), "r"(a[3]), "r"(b[0]), "r"(b[1]));
}

// ---------------------------------------------------------------------------
// LayerNorm: one block per row; writes split-bf16 (hi, lo)
// ---------------------------------------------------------------------------
__global__ __launch_bounds__(256) void ln3_kernel(
    const float* __restrict__ q, const float* __restrict__ k,
    const float* __restrict__ v, const float* __restrict__ g,
    const float* __restrict__ beta)
{
    __shared__ float sbuf[8];
    int which = blockIdx.x >> 12;
    int row   = blockIdx.x & 4095;
    const float* x =
        (which == 0 ? q : which == 1 ? k : v) + (size_t)row * ISZ;
    bf16* ohi = g_xhi + (size_t)which * ROWS * ISZ + (size_t)row * ISZ;
    bf16* olo = g_xlo + (size_t)which * ROWS * ISZ + (size_t)row * ISZ;

    int tid  = threadIdx.x;
    int lane = tid & 31, wid = tid >> 5;

    float vals[4];
    float s = 0.f;
#pragma unroll
    for (int i = 0; i < 4; i++) { vals[i] = x[tid + i * 256]; s += vals[i]; }
#pragma unroll
    for (int o = 16; o > 0; o >>= 1) s += __shfl_xor_sync(0xffffffffu, s, o);
    if (lane == 0) sbuf[wid] = s;
    __syncthreads();
    if (tid < 32) {
        float t = (tid < 8) ? sbuf[tid] : 0.f;
#pragma unroll
        for (int o = 4; o > 0; o >>= 1) t += __shfl_xor_sync(0xffffffffu, t, o);
        if (tid == 0) sbuf[0] = t;
    }
    __syncthreads();
    float mu = sbuf[0] * (1.f / ISZ);
    __syncthreads();

    float sq = 0.f;
#pragma unroll
    for (int i = 0; i < 4; i++) { float d = vals[i] - mu; sq += d * d; }
#pragma unroll
    for (int o = 16; o > 0; o >>= 1) sq += __shfl_xor_sync(0xffffffffu, sq, o);
    if (lane == 0) sbuf[wid] = sq;
    __syncthreads();
    if (tid < 32) {
        float t = (tid < 8) ? sbuf[tid] : 0.f;
#pragma unroll
        for (int o = 4; o > 0; o >>= 1) t += __shfl_xor_sync(0xffffffffu, t, o);
        if (tid == 0) sbuf[0] = t;
    }
    __syncthreads();
    float rstd = rsqrtf(sbuf[0] * (1.f / ISZ) + 1e-5f);

#pragma unroll
    for (int i = 0; i < 4; i++) {
        int idx = tid + i * 256;
        float y = (vals[i] - mu) * rstd * g[idx] + beta[idx];
        bf16 hi = __float2bfloat16(y);
        ohi[idx] = hi;
        olo[idx] = __float2bfloat16(y - __bfloat162float(hi));
    }
}

// ---------------------------------------------------------------------------
// Weight transpose + split: W[K][N] fp32 -> Wt_hi/lo[N][K] bf16
// ---------------------------------------------------------------------------
__global__ __launch_bounds__(256) void wconv_kernel(
    const float* __restrict__ W0, const float* __restrict__ W1,
    const float* __restrict__ W2, const float* __restrict__ W3)
{
    __shared__ float tile[32][33];
    int mat = blockIdx.z;
    const float* W = (mat == 0 ? W0 : mat == 1 ? W1 : mat == 2 ? W2 : W3);
    bf16* oh = g_wth + (size_t)mat * ISZ * ISZ;
    bf16* ol = g_wtl + (size_t)mat * ISZ * ISZ;

    int nt = blockIdx.x * 32, kt = blockIdx.y * 32;
    int tx = threadIdx.x & 31, ty = threadIdx.x >> 5;   // 32 x 8

#pragma unroll
    for (int i = 0; i < 4; i++)
        tile[ty + i * 8][tx] = W[(size_t)(kt + ty + i * 8) * ISZ + nt + tx];
    __syncthreads();
#pragma unroll
    for (int i = 0; i < 4; i++) {
        int n = nt + ty + i * 8;
        float w = tile[tx][ty + i * 8];
        bf16 hi = __float2bfloat16(w);
        oh[(size_t)n * ISZ + kt + tx] = hi;
        ol[(size_t)n * ISZ + kt + tx] = __float2bfloat16(w - __bfloat162float(hi));
    }
}

// ---------------------------------------------------------------------------
// Tensor-core GEMM via mma.sync (split bf16, 3 terms):
// C[M,N] = (Ahi+Alo)[M,K] @ (Bhi+Blo)[N,K]^T + bias[N], * mask[row]
// CTA 128x128, 8 warps (2x4), warp tile 64x32 (4x4 m16n8k16 tiles).
// K staged 64-wide, cp.async double-buffered. smem row stride 72 bf16
// (144B): ldmatrix rows hit bank offsets 4r mod 32 -> conflict-free.
// ---------------------------------------------------------------------------
#define GM 4096
#define GN 1024
#define GK 1024
#define KST 64
#define NT  (GK / KST)          // 16 stages
#define SK  72                  // smem stride in bf16
#define PBY (128 * SK * 2)      // bytes per piece: 18432
#define STB (4 * PBY)           // per stage: 73728
#define GSMEM (2 * STB)         // 147456

__global__ __launch_bounds__(256, 1) void gemm_mma(
    const bf16* __restrict__ Ahi, const bf16* __restrict__ Alo,
    const bf16* __restrict__ Bhi, const bf16* __restrict__ Blo,
    const float* __restrict__ bias, const float* __restrict__ mask,
    float* __restrict__ C)
{
    extern __shared__ __align__(128) char smc[];
    uint32_t sb = smem_u32(smc);

    int tid = threadIdx.x;
    int wid = tid >> 5, lane = tid & 31;
    int bn = blockIdx.x * 128, bm = blockIdx.y * 128;
    int warp_m = (wid >> 2) * 64;     // 0 or 64
    int warp_n = (wid & 3) * 32;      // 0,32,64,96

    const bf16* srcs[4] = {
        Ahi + (size_t)bm * GK, Alo + (size_t)bm * GK,
        Bhi + (size_t)bn * GK, Blo + (size_t)bn * GK };

    auto load_stage = [&](int t, int s) {
        int k0 = t * KST;
        uint32_t dbase = sb + s * STB;
#pragma unroll
        for (int buf = 0; buf < 4; buf++) {
#pragma unroll
            for (int i = 0; i < 4; i++) {
                int chunk = tid + i * 256;          // 0..1023
                int r = chunk >> 3, c = chunk & 7;  // row 0..127, 16B chunk 0..7
                const void* src = srcs[buf] + (size_t)r * GK + k0 + c * 8;
                uint32_t dst = dbase + buf * PBY + r * (SK * 2) + c * 16;
                cp_async16(dst, src);
            }
        }
    };

    float acc[4][4][4];
#pragma unroll
    for (int i = 0; i < 4; i++)
#pragma unroll
        for (int j = 0; j < 4; j++)
#pragma unroll
            for (int r = 0; r < 4; r++) acc[i][j][r] = 0.f;

    // ldmatrix lane-address components
    int a_row = lane & 15;              // row within 16
    int a_kh  = (lane >> 4) * 16;       // 0 or 16 bytes (k half)
    int b_row = lane & 7;
    int b_kh  = ((lane >> 3) & 1) * 16; // bytes

    load_stage(0, 0);
    cp_commit();

    for (int t = 0; t < NT; t++) {
        int s = t & 1;
        if (t + 1 < NT) { load_stage(t + 1, s ^ 1); cp_commit(); cp_wait1(); }
        else            { cp_wait0(); }
        __syncthreads();

        uint32_t st = sb + s * STB;
#pragma unroll
        for (int k16 = 0; k16 < 4; k16++) {
            uint32_t kb = k16 * 32;     // 16 bf16 = 32 bytes
            uint32_t ah[4][4], al[4][4], bh[4][2], bl[4][2];
#pragma unroll
            for (int mt = 0; mt < 4; mt++) {
                uint32_t ra = (warp_m + mt * 16 + a_row) * (SK * 2) + kb + a_kh;
                ldsm_x4(ah[mt][0], ah[mt][1], ah[mt][2], ah[mt][3], st + ra);
                ldsm_x4(al[mt][0], al[mt][1], al[mt][2], al[mt][3], st + PBY + ra);
            }
#pragma unroll
            for (int nt = 0; nt < 4; nt++) {
                uint32_t rb = (warp_n + nt * 8 + b_row) * (SK * 2) + kb + b_kh;
                ldsm_x2(bh[nt][0], bh[nt][1], st + 2 * PBY + rb);
                ldsm_x2(bl[nt][0], bl[nt][1], st + 3 * PBY + rb);
            }
#pragma unroll
            for (int mt = 0; mt < 4; mt++)
#pragma unroll
                for (int nt = 0; nt < 4; nt++) {
                    mma_bf16(acc[mt][nt], ah[mt], bh[nt]);
                    mma_bf16(acc[mt][nt], ah[mt], bl[nt]);
                    mma_bf16(acc[mt][nt], al[mt], bh[nt]);
                }
        }
        __syncthreads();   // stage s consumed before iter t+1 overwrites it
    }

    // epilogue: registers -> C with bias + row mask
#pragma unroll
    for (int mt = 0; mt < 4; mt++) {
        int r0 = bm + warp_m + mt * 16 + (lane >> 2);
        int r1 = r0 + 8;
        float mk0 = mask[r0], mk1 = mask[r1];
        float* c0 = C + (size_t)r0 * GN;
        float* c1 = C + (size_t)r1 * GN;
#pragma unroll
        for (int nt = 0; nt < 4; nt++) {
            int col = bn + warp_n + nt * 8 + (lane & 3) * 2;
            float2 o0, o1;
            o0.x = (acc[mt][nt][0] + bias[col + 0]) * mk0;
            o0.y = (acc[mt][nt][1] + bias[col + 1]) * mk0;
            o1.x = (acc[mt][nt][2] + bias[col + 0]) * mk1;
            o1.y = (acc[mt][nt][3] + bias[col + 1]) * mk1;
            *(float2*)(c0 + col) = o0;
            *(float2*)(c1 + col) = o1;
        }
    }
}

// ---------------------------------------------------------------------------
// Causal flash attention, register-tiled (fp32; bf16 hi/lo output)
// ---------------------------------------------------------------------------
#define APAD 66

__global__ __launch_bounds__(256) void attn_kernel(
    const float* __restrict__ Qw, const float* __restrict__ Kw,
    const float* __restrict__ Vw)
{
    extern __shared__ float smf[];
    float* Qs = smf;
    float* Ks = Qs + 64 * APAD;
    float* Vs = Ks + 64 * APAD;
    float* Ps = Vs + 64 * APAD;

    int qt = blockIdx.x;
    int bh = blockIdx.y;
    int b = bh >> 4, h = bh & 15;

    int tid = threadIdx.x;
    int tx = tid & 15, ty = tid >> 4;

    size_t tokBase = (size_t)b * SEQ;
    int colBase = h * HDIM;
    int q0 = qt * 64;

#pragma unroll
    for (int i = 0; i < 4; i++) {
        int p = i * 256 + tid;
        int r = p >> 4, f4 = p & 15;
        float4 qv = *(const float4*)(Qw + (tokBase + q0 + r) * ISZ + colBase + f4 * 4);
        Qs[r * APAD + f4 * 4 + 0] = qv.x;
        Qs[r * APAD + f4 * 4 + 1] = qv.y;
        Qs[r * APAD + f4 * 4 + 2] = qv.z;
        Qs[r * APAD + f4 * 4 + 3] = qv.w;
    }

    float m[4], l[4], acc[4][4];
#pragma unroll
    for (int i = 0; i < 4; i++) {
        m[i] = -3e38f; l[i] = 0.f;
#pragma unroll
        for (int j = 0; j < 4; j++) acc[i][j] = 0.f;
    }
    const float scale = 0.125f;

    for (int jt = 0; jt <= qt; jt++) {
        __syncthreads();
        int k0 = jt * 64;
#pragma unroll
        for (int i = 0; i < 4; i++) {
            int p = i * 256 + tid;
            int r = p >> 4, f4 = p & 15;
            float4 kv = *(const float4*)(Kw + (tokBase + k0 + r) * ISZ + colBase + f4 * 4);
            Ks[r * APAD + f4 * 4 + 0] = kv.x;
            Ks[r * APAD + f4 * 4 + 1] = kv.y;
            Ks[r * APAD + f4 * 4 + 2] = kv.z;
            Ks[r * APAD + f4 * 4 + 3] = kv.w;
            float4 vv = *(const float4*)(Vw + (tokBase + k0 + r) * ISZ + colBase + f4 * 4);
            Vs[r * APAD + f4 * 4 + 0] = vv.x;
            Vs[r * APAD + f4 * 4 + 1] = vv.y;
            Vs[r * APAD + f4 * 4 + 2] = vv.z;
            Vs[r * APAD + f4 * 4 + 3] = vv.w;
        }
        __syncthreads();

        float s4[4][4];
#pragma unroll
        for (int i = 0; i < 4; i++)
#pragma unroll
            for (int j = 0; j < 4; j++) s4[i][j] = 0.f;

#pragma unroll 8
        for (int k = 0; k < 64; k++) {
            float ra[4], rb[4];
#pragma unroll
            for (int i = 0; i < 4; i++) ra[i] = Qs[(ty * 4 + i) * APAD + k];
#pragma unroll
            for (int j = 0; j < 4; j++) rb[j] = Ks[(tx + 16 * j) * APAD + k];
#pragma unroll
            for (int i = 0; i < 4; i++)
#pragma unroll
                for (int j = 0; j < 4; j++) s4[i][j] += ra[i] * rb[j];
        }

        bool diag = (jt == qt);
#pragma unroll
        for (int i = 0; i < 4; i++) {
            int R = ty * 4 + i;
            float mx = -3e38f;
#pragma unroll
            for (int j = 0; j < 4; j++) {
                float v = s4[i][j] * scale;
                if (diag && (tx + 16 * j) > R) v = -3e38f;
                s4[i][j] = v;
                mx = fmaxf(mx, v);
            }
            mx = fmaxf(mx, __shfl_xor_sync(0xffffffffu, mx, 1));
            mx = fmaxf(mx, __shfl_xor_sync(0xffffffffu, mx, 2));
            mx = fmaxf(mx, __shfl_xor_sync(0xffffffffu, mx, 4));
            mx = fmaxf(mx, __shfl_xor_sync(0xffffffffu, mx, 8));

            float mnew = fmaxf(m[i], mx);
            float corr = __expf(m[i] - mnew);
            float ts = 0.f;
#pragma unroll
            for (int j = 0; j < 4; j++) {
                float pv = __expf(s4[i][j] - mnew);
                Ps[R * APAD + tx + 16 * j] = pv;
                ts += pv;
            }
            ts += __shfl_xor_sync(0xffffffffu, ts, 1);
            ts += __shfl_xor_sync(0xffffffffu, ts, 2);
            ts += __shfl_xor_sync(0xffffffffu, ts, 4);
            ts += __shfl_xor_sync(0xffffffffu, ts, 8);

            l[i] = l[i] * corr + ts;
            m[i] = mnew;
#pragma unroll
            for (int j = 0; j < 4; j++) acc[i][j] *= corr;
        }
        __syncthreads();

#pragma unroll 8
        for (int k2 = 0; k2 < 64; k2++) {
            float ra[4], rb[4];
#pragma unroll
            for (int i = 0; i < 4; i++) ra[i] = Ps[(ty * 4 + i) * APAD + k2];
#pragma unroll
            for (int j = 0; j < 4; j++) rb[j] = Vs[k2 * APAD + tx + 16 * j];
#pragma unroll
            for (int i = 0; i < 4; i++)
#pragma unroll
                for (int j = 0; j < 4; j++) acc[i][j] += ra[i] * rb[j];
        }
    }

#pragma unroll
    for (int i = 0; i < 4; i++) {
        float inv = 1.f / l[i];
        size_t rbase = (tokBase + q0 + ty * 4 + i) * ISZ + colBase;
#pragma unroll
        for (int j = 0; j < 4; j++) {
            float y = acc[i][j] * inv;
            bf16 hi = __float2bfloat16(y);
            g_aoh[rbase + tx + 16 * j] = hi;
            g_aol[rbase + tx + 16 * j] = __float2bfloat16(y - __bfloat162float(hi));
        }
    }
}

// ---------------------------------------------------------------------------
// Launch
// ---------------------------------------------------------------------------
template <typename T> static T* symaddr(const void* sym) {
    void* p; cudaGetSymbolAddress(&p, sym); return (T*)p;
}

extern "C" void kernel_launch(void* const* d_in, const int* in_sizes, int n_in,
                              void* d_out, int out_size)
{
    const float* q       = (const float*)d_in[0];
    const float* k       = (const float*)d_in[1];
    const float* v       = (const float*)d_in[2];
    const float* q_mask  = (const float*)d_in[3];
    const float* kv_mask = (const float*)d_in[4];
    const float* ln_g    = (const float*)d_in[6];
    const float* ln_b    = (const float*)d_in[7];
    const float* Wq      = (const float*)d_in[8];
    const float* bq      = (const float*)d_in[9];
    const float* Wk      = (const float*)d_in[10];
    const float* bk      = (const float*)d_in[11];
    const float* Wv      = (const float*)d_in[12];
    const float* bv      = (const float*)d_in[13];
    const float* Wo      = (const float*)d_in[14];
    const float* bo      = (const float*)d_in[15];
    float* out = (float*)d_out;

    bf16*  xhi = symaddr<bf16>(g_xhi);
    bf16*  xlo = symaddr<bf16>(g_xlo);
    bf16*  wth = symaddr<bf16>(g_wth);
    bf16*  wtl = symaddr<bf16>(g_wtl);
    float* qw  = symaddr<float>(g_qw);
    float* kw  = symaddr<float>(g_kw);
    float* vw  = symaddr<float>(g_vw);
    bf16*  aoh = symaddr<bf16>(g_aoh);
    bf16*  aol = symaddr<bf16>(g_aol);

    const size_t T = (size_t)ROWS * ISZ;    // 4M elements
    const size_t WSZ = (size_t)ISZ * ISZ;   // 1M elements

    // 1) LayerNorm -> split bf16
    ln3_kernel<<<3 * ROWS, 256>>>(q, k, v, ln_g, ln_b);

    // 2) Weight transpose + split
    wconv_kernel<<<dim3(32, 32, 4), 256>>>(Wq, Wk, Wv, Wo);

    // 3) QKV projections on tensor cores (mma.sync)
    cudaFuncSetAttribute(gemm_mma,
                         cudaFuncAttributeMaxDynamicSharedMemorySize, GSMEM);
    dim3 ggrid(GN / 128, GM / 128);
    gemm_mma<<<ggrid, 256, GSMEM>>>(xhi,         xlo,         wth,           wtl,           bq, q_mask,  qw);
    gemm_mma<<<ggrid, 256, GSMEM>>>(xhi + T,     xlo + T,     wth + WSZ,     wtl + WSZ,     bk, kv_mask, kw);
    gemm_mma<<<ggrid, 256, GSMEM>>>(xhi + 2 * T, xlo + 2 * T, wth + 2 * WSZ, wtl + 2 * WSZ, bv, kv_mask, vw);

    // 4) Causal flash attention -> split bf16
    int smem_bytes = 4 * 64 * APAD * (int)sizeof(float);
    cudaFuncSetAttribute(attn_kernel,
                         cudaFuncAttributeMaxDynamicSharedMemorySize, smem_bytes);
    dim3 agrid(SEQ / 64, BATCH * NHEAD);
    attn_kernel<<<agrid, 256, smem_bytes>>>(qw, kw, vw);

    // 5) Output projection straight into d_out
    gemm_mma<<<ggrid, 256, GSMEM>>>(aoh, aol, wth + 3 * WSZ, wtl + 3 * WSZ, bo, kv_mask, out);
}

// round 6
// speedup vs baseline: 3.8908x; 1.8666x over previous
#include <cuda_runtime.h>
#include <cuda_bf16.h>
#include <cuda_fp16.h>
#include <math.h>
#include <stdint.h>

// Problem constants
#define BATCH 2
#define SEQ   2048
#define ISZ   1024
#define NHEAD 16
#define HDIM  64
#define ROWS  (BATCH*SEQ)      // 4096

typedef __nv_bfloat16 bf16;

// ---------------------------------------------------------------------------
// Scratch (device globals: allocation-free per harness rules)
// ---------------------------------------------------------------------------
__device__ bf16  g_xhi[(size_t)3*ROWS*ISZ];   // LN outputs hi (q,k,v)
__device__ bf16  g_xlo[(size_t)3*ROWS*ISZ];   // LN outputs lo
__device__ bf16  g_wth[(size_t)4*ISZ*ISZ];    // W^T hi (Wq,Wk,Wv,Wo)
__device__ bf16  g_wtl[(size_t)4*ISZ*ISZ];    // W^T lo
__device__ float g_qw[(size_t)ROWS*ISZ];
__device__ float g_kw[(size_t)ROWS*ISZ];
__device__ float g_vw[(size_t)ROWS*ISZ];
__device__ bf16  g_aoh[(size_t)ROWS*ISZ];     // attention out hi
__device__ bf16  g_aol[(size_t)ROWS*ISZ];     // attention out lo

// ---------------------------------------------------------------------------
// PTX helpers (Ampere-compatible: cp.async, ldmatrix, mma.sync)
// ---------------------------------------------------------------------------
__device__ __forceinline__ uint32_t smem_u32(const void* p) {
    return (uint32_t)__cvta_generic_to_shared(p);
}
__device__ __forceinline__ void cp_async16(uint32_t dst, const void* src) {
    asm volatile("cp.async.cg.shared.global [%0], [%1], 16;\n" :: "r"(dst), "l"(src));
}
__device__ __forceinline__ void cp_commit() {
    asm volatile("cp.async.commit_group;\n");
}
__device__ __forceinline__ void cp_wait1() {
    asm volatile("cp.async.wait_group 1;\n");
}
__device__ __forceinline__ void cp_wait0() {
    asm volatile("cp.async.wait_group 0;\n");
}
__device__ __forceinline__ void ldsm_x4(uint32_t& r0, uint32_t& r1,
                                        uint32_t& r2, uint32_t& r3, uint32_t a) {
    asm volatile("ldmatrix.sync.aligned.m8n8.x4.shared.b16 {%0,%1,%2,%3}, [%4];"
                 : "=r"(r0), "=r"(r1), "=r"(r2), "=r"(r3) : "r"(a));
}
__device__ __forceinline__ void ldsm_x2(uint32_t& r0, uint32_t& r1, uint32_t a) {
    asm volatile("ldmatrix.sync.aligned.m8n8.x2.shared.b16 {%0,%1}, [%2];"
                 : "=r"(r0), "=r"(r1) : "r"(a));
}
__device__ __forceinline__ void ldsm_x2t(uint32_t& r0, uint32_t& r1, uint32_t a) {
    asm volatile("ldmatrix.sync.aligned.m8n8.x2.trans.shared.b16 {%0,%1}, [%2];"
                 : "=r"(r0), "=r"(r1) : "r"(a));
}
__device__ __forceinline__ void mma_bf16(float* d, const uint32_t* a, const uint32_t* b) {
    asm volatile("mma.sync.aligned.m16n8k16.row.col.f32.bf16.bf16.f32 "
                 "{%0,%1,%2,%3}, {%4,%5,%6,%7}, {%8,%9}, {%0,%1,%2,%3};"
                 : "+f"(d[0]), "+f"(d[1]), "+f"(d[2]), "+f"(d[3])
                 : "r"(a[0]), "r"(a[1]), "r"(a[2]), "r"(a[3]), "r"(b[0]), "r"(b[1]));
}
__device__ __forceinline__ void mma_f16(float* d, const uint32_t* a, const uint32_t* b) {
    asm volatile("mma.sync.aligned.m16n8k16.row.col.f32.f16.f16.f32 "
                 "{%0,%1,%2,%3}, {%4,%5,%6,%7}, {%8,%9}, {%0,%1,%2,%3};"
                 : "+f"(d[0]), "+f"(d[1]), "+f"(d[2]), "+f"(d[3])
                 : "r"(a[0]), "r"(a[1]), "r"(a[2]), "r"(a[3]), "r"(b[0]), "r"(b[1]));
}
__device__ __forceinline__ uint32_t h2pack(float a, float b) {
    __half2 h = __floats2half2_rn(a, b);
    return *(uint32_t*)&h;
}

// ---------------------------------------------------------------------------
// LayerNorm: one block per row; writes split-bf16 (hi, lo)
// ---------------------------------------------------------------------------
__global__ __launch_bounds__(256) void ln3_kernel(
    const float* __restrict__ q, const float* __restrict__ k,
    const float* __restrict__ v, const float* __restrict__ g,
    const float* __restrict__ beta)
{
    __shared__ float sbuf[8];
    int which = blockIdx.x >> 12;
    int row   = blockIdx.x & 4095;
    const float* x =
        (which == 0 ? q : which == 1 ? k : v) + (size_t)row * ISZ;
    bf16* ohi = g_xhi + (size_t)which * ROWS * ISZ + (size_t)row * ISZ;
    bf16* olo = g_xlo + (size_t)which * ROWS * ISZ + (size_t)row * ISZ;

    int tid  = threadIdx.x;
    int lane = tid & 31, wid = tid >> 5;

    float vals[4];
    float s = 0.f;
#pragma unroll
    for (int i = 0; i < 4; i++) { vals[i] = x[tid + i * 256]; s += vals[i]; }
#pragma unroll
    for (int o = 16; o > 0; o >>= 1) s += __shfl_xor_sync(0xffffffffu, s, o);
    if (lane == 0) sbuf[wid] = s;
    __syncthreads();
    if (tid < 32) {
        float t = (tid < 8) ? sbuf[tid] : 0.f;
#pragma unroll
        for (int o = 4; o > 0; o >>= 1) t += __shfl_xor_sync(0xffffffffu, t, o);
        if (tid == 0) sbuf[0] = t;
    }
    __syncthreads();
    float mu = sbuf[0] * (1.f / ISZ);
    __syncthreads();

    float sq = 0.f;
#pragma unroll
    for (int i = 0; i < 4; i++) { float d = vals[i] - mu; sq += d * d; }
#pragma unroll
    for (int o = 16; o > 0; o >>= 1) sq += __shfl_xor_sync(0xffffffffu, sq, o);
    if (lane == 0) sbuf[wid] = sq;
    __syncthreads();
    if (tid < 32) {
        float t = (tid < 8) ? sbuf[tid] : 0.f;
#pragma unroll
        for (int o = 4; o > 0; o >>= 1) t += __shfl_xor_sync(0xffffffffu, t, o);
        if (tid == 0) sbuf[0] = t;
    }
    __syncthreads();
    float rstd = rsqrtf(sbuf[0] * (1.f / ISZ) + 1e-5f);

#pragma unroll
    for (int i = 0; i < 4; i++) {
        int idx = tid + i * 256;
        float y = (vals[i] - mu) * rstd * g[idx] + beta[idx];
        bf16 hi = __float2bfloat16(y);
        ohi[idx] = hi;
        olo[idx] = __float2bfloat16(y - __bfloat162float(hi));
    }
}

// ---------------------------------------------------------------------------
// Weight transpose + split: W[K][N] fp32 -> Wt_hi/lo[N][K] bf16
// ---------------------------------------------------------------------------
__global__ __launch_bounds__(256) void wconv_kernel(
    const float* __restrict__ W0, const float* __restrict__ W1,
    const float* __restrict__ W2, const float* __restrict__ W3)
{
    __shared__ float tile[32][33];
    int mat = blockIdx.z;
    const float* W = (mat == 0 ? W0 : mat == 1 ? W1 : mat == 2 ? W2 : W3);
    bf16* oh = g_wth + (size_t)mat * ISZ * ISZ;
    bf16* ol = g_wtl + (size_t)mat * ISZ * ISZ;

    int nt = blockIdx.x * 32, kt = blockIdx.y * 32;
    int tx = threadIdx.x & 31, ty = threadIdx.x >> 5;   // 32 x 8

#pragma unroll
    for (int i = 0; i < 4; i++)
        tile[ty + i * 8][tx] = W[(size_t)(kt + ty + i * 8) * ISZ + nt + tx];
    __syncthreads();
#pragma unroll
    for (int i = 0; i < 4; i++) {
        int n = nt + ty + i * 8;
        float w = tile[tx][ty + i * 8];
        bf16 hi = __float2bfloat16(w);
        oh[(size_t)n * ISZ + kt + tx] = hi;
        ol[(size_t)n * ISZ + kt + tx] = __float2bfloat16(w - __bfloat162float(hi));
    }
}

// ---------------------------------------------------------------------------
// Tensor-core GEMM via mma.sync (split bf16, 3 terms) — unchanged (proven)
// ---------------------------------------------------------------------------
#define GM 4096
#define GN 1024
#define GK 1024
#define KST 64
#define NT  (GK / KST)          // 16 stages
#define SK  72                  // smem stride in bf16
#define PBY (128 * SK * 2)      // bytes per piece: 18432
#define STB (4 * PBY)           // per stage: 73728
#define GSMEM (2 * STB)         // 147456

__global__ __launch_bounds__(256, 1) void gemm_mma(
    const bf16* __restrict__ Ahi, const bf16* __restrict__ Alo,
    const bf16* __restrict__ Bhi, const bf16* __restrict__ Blo,
    const float* __restrict__ bias, const float* __restrict__ mask,
    float* __restrict__ C)
{
    extern __shared__ __align__(128) char smc[];
    uint32_t sb = smem_u32(smc);

    int tid = threadIdx.x;
    int wid = tid >> 5, lane = tid & 31;
    int bn = blockIdx.x * 128, bm = blockIdx.y * 128;
    int warp_m = (wid >> 2) * 64;
    int warp_n = (wid & 3) * 32;

    const bf16* srcs[4] = {
        Ahi + (size_t)bm * GK, Alo + (size_t)bm * GK,
        Bhi + (size_t)bn * GK, Blo + (size_t)bn * GK };

    auto load_stage = [&](int t, int s) {
        int k0 = t * KST;
        uint32_t dbase = sb + s * STB;
#pragma unroll
        for (int buf = 0; buf < 4; buf++) {
#pragma unroll
            for (int i = 0; i < 4; i++) {
                int chunk = tid + i * 256;
                int r = chunk >> 3, c = chunk & 7;
                const void* src = srcs[buf] + (size_t)r * GK + k0 + c * 8;
                uint32_t dst = dbase + buf * PBY + r * (SK * 2) + c * 16;
                cp_async16(dst, src);
            }
        }
    };

    float acc[4][4][4];
#pragma unroll
    for (int i = 0; i < 4; i++)
#pragma unroll
        for (int j = 0; j < 4; j++)
#pragma unroll
            for (int r = 0; r < 4; r++) acc[i][j][r] = 0.f;

    int a_row = lane & 15;
    int a_kh  = (lane >> 4) * 16;
    int b_row = lane & 7;
    int b_kh  = ((lane >> 3) & 1) * 16;

    load_stage(0, 0);
    cp_commit();

    for (int t = 0; t < NT; t++) {
        int s = t & 1;
        if (t + 1 < NT) { load_stage(t + 1, s ^ 1); cp_commit(); cp_wait1(); }
        else            { cp_wait0(); }
        __syncthreads();

        uint32_t st = sb + s * STB;
#pragma unroll
        for (int k16 = 0; k16 < 4; k16++) {
            uint32_t kb = k16 * 32;
            uint32_t ah[4][4], al[4][4], bh[4][2], bl[4][2];
#pragma unroll
            for (int mt = 0; mt < 4; mt++) {
                uint32_t ra = (warp_m + mt * 16 + a_row) * (SK * 2) + kb + a_kh;
                ldsm_x4(ah[mt][0], ah[mt][1], ah[mt][2], ah[mt][3], st + ra);
                ldsm_x4(al[mt][0], al[mt][1], al[mt][2], al[mt][3], st + PBY + ra);
            }
#pragma unroll
            for (int nt = 0; nt < 4; nt++) {
                uint32_t rb = (warp_n + nt * 8 + b_row) * (SK * 2) + kb + b_kh;
                ldsm_x2(bh[nt][0], bh[nt][1], st + 2 * PBY + rb);
                ldsm_x2(bl[nt][0], bl[nt][1], st + 3 * PBY + rb);
            }
#pragma unroll
            for (int mt = 0; mt < 4; mt++)
#pragma unroll
                for (int nt = 0; nt < 4; nt++) {
                    mma_bf16(acc[mt][nt], ah[mt], bh[nt]);
                    mma_bf16(acc[mt][nt], ah[mt], bl[nt]);
                    mma_bf16(acc[mt][nt], al[mt], bh[nt]);
                }
        }
        __syncthreads();
    }

#pragma unroll
    for (int mt = 0; mt < 4; mt++) {
        int r0 = bm + warp_m + mt * 16 + (lane >> 2);
        int r1 = r0 + 8;
        float mk0 = mask[r0], mk1 = mask[r1];
        float* c0 = C + (size_t)r0 * GN;
        float* c1 = C + (size_t)r1 * GN;
#pragma unroll
        for (int nt = 0; nt < 4; nt++) {
            int col = bn + warp_n + nt * 8 + (lane & 3) * 2;
            float2 o0, o1;
            o0.x = (acc[mt][nt][0] + bias[col + 0]) * mk0;
            o0.y = (acc[mt][nt][1] + bias[col + 1]) * mk0;
            o1.x = (acc[mt][nt][2] + bias[col + 0]) * mk1;
            o1.y = (acc[mt][nt][3] + bias[col + 1]) * mk1;
            *(float2*)(c0 + col) = o0;
            *(float2*)(c1 + col) = o1;
        }
    }
}

// ---------------------------------------------------------------------------
// Flash attention on tensor cores (fp16 mma.sync).
// Block = 128 q-rows x (b,h). 8 warps x m16. Q frags (hi/lo fp16, scale
// folded) held in registers for the whole block; K,V single fp16 in smem.
// S accums reinterpreted as P A-frags (FA2 layout identity); P split hi/lo.
// ---------------------------------------------------------------------------
#define AST 72   // smem row stride in halves (144 B)

__global__ __launch_bounds__(256) void attn_mma(
    const float* __restrict__ Qw, const float* __restrict__ Kw,
    const float* __restrict__ Vw)
{
    __shared__ __align__(16) __half asm_h[128 * AST * 2];  // 36864 B
    __half* Qh = asm_h;                  // [128][AST] (prologue only)
    __half* Ql = asm_h + 128 * AST;      // [128][AST] (prologue only)
    __half* Ks = asm_h;                  // [64][AST]  (reuses Qh space)
    __half* Vs = asm_h + 64 * AST;       // [64][AST]

    int tid = threadIdx.x;
    int wid = tid >> 5, lane = tid & 31;
    int qb = (int)(gridDim.x - 1 - blockIdx.x);   // heavy blocks first
    int bh = blockIdx.y;
    int b = bh >> 4, h = bh & 15;

    size_t tokQ = (size_t)b * SEQ + qb * 128;
    int colBase = h * HDIM;

    // ---- stage Q (scaled by 0.125, split fp16 hi/lo) ----
#pragma unroll
    for (int i = 0; i < 8; i++) {
        int p = tid + i * 256;           // 0..2047 = 128 rows x 16 float4
        int r = p >> 4, c4 = p & 15;
        float4 qv = *(const float4*)(Qw + (tokQ + r) * ISZ + colBase + c4 * 4);
        float y[4] = { qv.x * 0.125f, qv.y * 0.125f, qv.z * 0.125f, qv.w * 0.125f };
#pragma unroll
        for (int e = 0; e < 4; e++) {
            __half hi = __float2half_rn(y[e]);
            Qh[r * AST + c4 * 4 + e] = hi;
            Ql[r * AST + c4 * 4 + e] = __float2half_rn(y[e] - __half2float(hi));
        }
    }
    __syncthreads();

    // ---- Q fragments to registers (4 k16 tiles x 4 regs, hi+lo) ----
    uint32_t qfh[4][4], qfl[4][4];
    {
        uint32_t qb0 = smem_u32(Qh);
        uint32_t qb1 = smem_u32(Ql);
        int a_row = lane & 15;
        int a_kh  = (lane >> 4) * 16;    // bytes
#pragma unroll
        for (int j = 0; j < 4; j++) {
            uint32_t off = (wid * 16 + a_row) * (AST * 2) + j * 32 + a_kh;
            ldsm_x4(qfh[j][0], qfh[j][1], qfh[j][2], qfh[j][3], qb0 + off);
            ldsm_x4(qfl[j][0], qfl[j][1], qfl[j][2], qfl[j][3], qb1 + off);
        }
    }

    float O[8][4];
#pragma unroll
    for (int nt = 0; nt < 8; nt++)
#pragma unroll
        for (int e = 0; e < 4; e++) O[nt][e] = 0.f;
    float mrow[2] = { -3e38f, -3e38f };
    float lrow[2] = { 0.f, 0.f };

    uint32_t ksb = smem_u32(Ks);
    uint32_t vsb = smem_u32(Vs);
    int b_row = lane & 7;
    int b_kh  = ((lane >> 3) & 1) * 16;

    int nkt = 2 * qb + 2;
    for (int kt = 0; kt < nkt; kt++) {
        __syncthreads();    // all warps done reading previous K/V (and Q frags)
        size_t tokK = (size_t)b * SEQ + kt * 64;
        // stage K,V fp16 (64 rows x 16 float4 each)
#pragma unroll
        for (int i = 0; i < 4; i++) {
            int p = tid + i * 256;       // 0..1023
            int r = p >> 4, c4 = p & 15;
            float4 kv = *(const float4*)(Kw + (tokK + r) * ISZ + colBase + c4 * 4);
            *(uint32_t*)(Ks + r * AST + c4 * 4)     = h2pack(kv.x, kv.y);
            *(uint32_t*)(Ks + r * AST + c4 * 4 + 2) = h2pack(kv.z, kv.w);
            float4 vv = *(const float4*)(Vw + (tokK + r) * ISZ + colBase + c4 * 4);
            *(uint32_t*)(Vs + r * AST + c4 * 4)     = h2pack(vv.x, vv.y);
            *(uint32_t*)(Vs + r * AST + c4 * 4 + 2) = h2pack(vv.z, vv.w);
        }
        __syncthreads();

        // ---- S = (Qhi+Qlo) @ K^T  (scale already folded into Q) ----
        float S[8][4];
#pragma unroll
        for (int nt = 0; nt < 8; nt++)
#pragma unroll
            for (int e = 0; e < 4; e++) S[nt][e] = 0.f;

#pragma unroll
        for (int j = 0; j < 4; j++) {
#pragma unroll
            for (int nt = 0; nt < 8; nt++) {
                uint32_t kf[2];
                ldsm_x2(kf[0], kf[1], ksb + (nt * 8 + b_row) * (AST * 2) + j * 32 + b_kh);
                mma_f16(S[nt], qfh[j], kf);
                mma_f16(S[nt], qfl[j], kf);
            }
        }

        // ---- causal mask (diagonal tiles only) ----
        if (kt >= 2 * qb) {
            int Rb = qb * 128 + wid * 16 + (lane >> 2);
#pragma unroll
            for (int nt = 0; nt < 8; nt++)
#pragma unroll
                for (int e = 0; e < 4; e++) {
                    int R = Rb + (e >> 1) * 8;
                    int C = kt * 64 + nt * 8 + 2 * (lane & 3) + (e & 1);
                    if (C > R) S[nt][e] = -3e38f;
                }
        }

        // ---- online softmax (rows r0, r1 per thread; 4 lanes share a row) ----
#pragma unroll
        for (int hh = 0; hh < 2; hh++) {
            float mx = -3e38f;
#pragma unroll
            for (int nt = 0; nt < 8; nt++) {
                mx = fmaxf(mx, S[nt][2 * hh]);
                mx = fmaxf(mx, S[nt][2 * hh + 1]);
            }
            mx = fmaxf(mx, __shfl_xor_sync(0xffffffffu, mx, 1));
            mx = fmaxf(mx, __shfl_xor_sync(0xffffffffu, mx, 2));

            float mnew = fmaxf(mrow[hh], mx);
            float corr = __expf(mrow[hh] - mnew);
            float ts = 0.f;
#pragma unroll
            for (int nt = 0; nt < 8; nt++) {
                float p0 = __expf(S[nt][2 * hh]     - mnew);
                float p1 = __expf(S[nt][2 * hh + 1] - mnew);
                S[nt][2 * hh]     = p0;
                S[nt][2 * hh + 1] = p1;
                ts += p0 + p1;
            }
            ts += __shfl_xor_sync(0xffffffffu, ts, 1);
            ts += __shfl_xor_sync(0xffffffffu, ts, 2);

            lrow[hh] = lrow[hh] * corr + ts;
            mrow[hh] = mnew;
#pragma unroll
            for (int nt = 0; nt < 8; nt++) {
                O[nt][2 * hh]     *= corr;
                O[nt][2 * hh + 1] *= corr;
            }
        }

        // ---- O += (Phi+Plo) @ V ----
#pragma unroll
        for (int j = 0; j < 4; j++) {
            // P A-frags from S accums (FA2 layout identity), split hi/lo
            uint32_t ph[4], pl[4];
#pragma unroll
            for (int r = 0; r < 4; r++) {
                int nt = 2 * j + (r >> 1);
                int e0 = (r & 1) * 2;
                float p0 = S[nt][e0], p1 = S[nt][e0 + 1];
                __half h0 = __float2half_rn(p0), h1 = __float2half_rn(p1);
                __half2 hp = __halves2half2(h0, h1);
                ph[r] = *(uint32_t*)&hp;
                pl[r] = h2pack(p0 - __half2float(h0), p1 - __half2float(h1));
            }
            // reorder to A layout: {(r0,klo),(r1,klo),(r0,khi),(r1,khi)}
            uint32_t pa[4] = { ph[0], ph[1], ph[2], ph[3] };
            uint32_t pb[4] = { pl[0], pl[1], pl[2], pl[3] };
#pragma unroll
            for (int nt = 0; nt < 8; nt++) {
                uint32_t vf[2];
                ldsm_x2t(vf[0], vf[1], vsb + (j * 16 + (lane & 15)) * (AST * 2) + nt * 16);
                mma_f16(O[nt], pa, vf);
                mma_f16(O[nt], pb, vf);
            }
        }
    }

    // ---- epilogue: normalize, split bf16 hi/lo for the Wo GEMM ----
#pragma unroll
    for (int hh = 0; hh < 2; hh++) {
        float inv = 1.f / lrow[hh];
        size_t tok = tokQ + wid * 16 + (lane >> 2) + 8 * hh;
#pragma unroll
        for (int nt = 0; nt < 8; nt++) {
            int col = colBase + nt * 8 + 2 * (lane & 3);
            float y0 = O[nt][2 * hh] * inv;
            float y1 = O[nt][2 * hh + 1] * inv;
            bf16 h0 = __float2bfloat16(y0);
            bf16 h1 = __float2bfloat16(y1);
            __nv_bfloat162 hv = { h0, h1 };
            __nv_bfloat162 lv = { __float2bfloat16(y0 - __bfloat162float(h0)),
                                  __float2bfloat16(y1 - __bfloat162float(h1)) };
            *(__nv_bfloat162*)(g_aoh + tok * ISZ + col) = hv;
            *(__nv_bfloat162*)(g_aol + tok * ISZ + col) = lv;
        }
    }
}

// ---------------------------------------------------------------------------
// Launch
// ---------------------------------------------------------------------------
template <typename T> static T* symaddr(const void* sym) {
    void* p; cudaGetSymbolAddress(&p, sym); return (T*)p;
}

extern "C" void kernel_launch(void* const* d_in, const int* in_sizes, int n_in,
                              void* d_out, int out_size)
{
    const float* q       = (const float*)d_in[0];
    const float* k       = (const float*)d_in[1];
    const float* v       = (const float*)d_in[2];
    const float* q_mask  = (const float*)d_in[3];
    const float* kv_mask = (const float*)d_in[4];
    const float* ln_g    = (const float*)d_in[6];
    const float* ln_b    = (const float*)d_in[7];
    const float* Wq      = (const float*)d_in[8];
    const float* bq      = (const float*)d_in[9];
    const float* Wk      = (const float*)d_in[10];
    const float* bk      = (const float*)d_in[11];
    const float* Wv      = (const float*)d_in[12];
    const float* bv      = (const float*)d_in[13];
    const float* Wo      = (const float*)d_in[14];
    const float* bo      = (const float*)d_in[15];
    float* out = (float*)d_out;

    bf16*  xhi = symaddr<bf16>(g_xhi);
    bf16*  xlo = symaddr<bf16>(g_xlo);
    bf16*  wth = symaddr<bf16>(g_wth);
    bf16*  wtl = symaddr<bf16>(g_wtl);
    float* qw  = symaddr<float>(g_qw);
    float* kw  = symaddr<float>(g_kw);
    float* vw  = symaddr<float>(g_vw);
    bf16*  aoh = symaddr<bf16>(g_aoh);
    bf16*  aol = symaddr<bf16>(g_aol);

    const size_t T = (size_t)ROWS * ISZ;
    const size_t WSZ = (size_t)ISZ * ISZ;

    // 1) LayerNorm -> split bf16
    ln3_kernel<<<3 * ROWS, 256>>>(q, k, v, ln_g, ln_b);

    // 2) Weight transpose + split
    wconv_kernel<<<dim3(32, 32, 4), 256>>>(Wq, Wk, Wv, Wo);

    // 3) QKV projections (mma.sync)
    cudaFuncSetAttribute(gemm_mma,
                         cudaFuncAttributeMaxDynamicSharedMemorySize, GSMEM);
    dim3 ggrid(GN / 128, GM / 128);
    gemm_mma<<<ggrid, 256, GSMEM>>>(xhi,         xlo,         wth,           wtl,           bq, q_mask,  qw);
    gemm_mma<<<ggrid, 256, GSMEM>>>(xhi + T,     xlo + T,     wth + WSZ,     wtl + WSZ,     bk, kv_mask, kw);
    gemm_mma<<<ggrid, 256, GSMEM>>>(xhi + 2 * T, xlo + 2 * T, wth + 2 * WSZ, wtl + 2 * WSZ, bv, kv_mask, vw);

    // 4) Flash attention on tensor cores -> split bf16
    dim3 agrid(SEQ / 128, BATCH * NHEAD);
    attn_mma<<<agrid, 256>>>(qw, kw, vw);

    // 5) Output projection straight into d_out
    gemm_mma<<<ggrid, 256, GSMEM>>>(aoh, aol, wth + 3 * WSZ, wtl + 3 * WSZ, bo, kv_mask, out);
}